// round 15
// baseline (speedup 1.0000x reference)
#include <cuda_runtime.h>
#include <cuda_bf16.h>
#include <math.h>

// ConsensusField3D: per-voxel quaternion slerp + gated blend.
// B=2, K=3, D=H=W=96, V=96^3=884736.
// R12 -> R13 (memory-bound now: DRAM 67.8%, issue 39.6%):
//   4 voxels/thread (float4): 14 LDG.128 + 16 STG.128 per thread, halves
//   request count per byte; __ldcs/__stcs streaming hints (zero reuse).

static constexpr int Dv = 96;
static constexpr int Vv = Dv * Dv * Dv;   // 884736 (div by 4)
static constexpr int Bv = 2;
static constexpr int Kv = 3;
static constexpr int H4 = Vv / 4;         // float4 elems per plane = 221184

__device__ __forceinline__ void voxel_math(
    float qa0, float qa1, float qa2, float qa3,
    float qq0, float qq1, float qq2, float qq3,
    float rv0, float rv1, float rv2,
    float rr0, float rr1, float rr2,
    float w0, float w1, float w2, float w3b,
    float Rn[9], float qo[4], float& omega)
{
    // normalize quats: 1/(||q||+eps) ~= rsqrt(||q||^2) (rel diff ~1e-6)
    float ia = rsqrtf(qa0*qa0 + qa1*qa1 + qa2*qa2 + qa3*qa3);
    float ib = rsqrtf(qq0*qq0 + qq1*qq1 + qq2*qq2 + qq3*qq3);
    qa0 *= ia; qa1 *= ia; qa2 *= ia; qa3 *= ia;
    qq0 *= ib; qq1 *= ib; qq2 *= ib; qq3 *= ib;

    float dotq = qa0*qq0 + qa1*qq1 + qa2*qq2 + qa3*qq3;
    float ad   = fabsf(dotq);
    float cfeat = fminf(ad, 1.0f);

    float rm  = (rv0 + rv1 + rv2) * (1.0f / 3.0f);
    float rmr = (rr0 + rr1 + rr2) * (1.0f / 3.0f);

    float z = fmaf(rm, w0, fmaf(rmr, w1, fmaf(cfeat, w2, w3b)));
    omega = __fdividef(1.0f, 1.0f + __expf(-z));        // sigmoid
    float t = omega;

    // slerp. d = clip(|dot|, 0, 1-1e-7); flip q1 if dot<0.
    float sgn = (dotq < 0.0f) ? -1.0f : 1.0f;
    float dcl = fminf(ad, 1.0f - 1e-7f);

    // theta = acos(dcl) via A&S 4.4.45: sqrt(1-x)*poly3(x), err <= 6.7e-5
    float omx = 1.0f - dcl;                              // >= 1e-7
    float sq_omx = omx * rsqrtf(omx);                    // sqrt(1-x)
    float poly = fmaf(fmaf(fmaf(-0.0187293f, dcl, 0.0742610f),
                           dcl, -0.2121144f), dcl, 1.5707288f);
    float theta = sq_omx * poly;

    // sin(theta) = sqrt((1-d)(1+d)) >= 4.47e-4 (lerp branch provably dead)
    float st2 = omx * (1.0f + dcl);
    float inv_sin = rsqrtf(st2);

    float s_t  = __sinf(t * theta);
    float s_1t = __sinf((1.0f - t) * theta);
    float c0 = s_t * inv_sin;
    float c1 = s_1t * inv_sin * sgn;

    qo[0] = c0 * qa0 + c1 * qq0;
    qo[1] = c0 * qa1 + c1 * qq1;
    qo[2] = c0 * qa2 + c1 * qq2;
    qo[3] = c0 * qa3 + c1 * qq3;

    float io = rsqrtf(qo[0]*qo[0] + qo[1]*qo[1] + qo[2]*qo[2] + qo[3]*qo[3]);
#pragma unroll
    for (int c = 0; c < 4; c++) qo[c] *= io;

    // quat -> rotation matrix
    float w = qo[0], x = qo[1], y = qo[2], zq = qo[3];
    float xx = x*x, yy = y*y, z2 = zq*zq;
    float xy = x*y, xz = x*zq, yz = y*zq;
    float wx = w*x, wy = w*y, wz = w*zq;

    float R[3][3];
    R[0][0] = 1.0f - 2.0f*(yy + z2);
    R[0][1] = 2.0f*(xy - wz);
    R[0][2] = 2.0f*(xz + wy);
    R[1][0] = 2.0f*(xy + wz);
    R[1][1] = 1.0f - 2.0f*(xx + z2);
    R[1][2] = 2.0f*(yz - wx);
    R[2][0] = 2.0f*(xz - wy);
    R[2][1] = 2.0f*(yz + wx);
    R[2][2] = 1.0f - 2.0f*(xx + yy);

    // column-normalize (axis=-2); Rn stored output-ordered (j*3+i)
#pragma unroll
    for (int j = 0; j < 3; j++) {
        float cn = rsqrtf(R[0][j]*R[0][j] + R[1][j]*R[1][j] + R[2][j]*R[2][j]);
#pragma unroll
        for (int i = 0; i < 3; i++) {
            Rn[j*3 + i] = R[i][j] * cn;
        }
    }
}

__global__ __launch_bounds__(256)
void consensus_field_kernel(const float* __restrict__ r_in,
                            const float* __restrict__ q_in,
                            const float* __restrict__ r_ref,
                            const float* __restrict__ q_ref,
                            const float* __restrict__ gate_w,
                            const float* __restrict__ gate_b,
                            float* __restrict__ out)
{
    const int tid = blockIdx.x * blockDim.x + threadIdx.x;
    const int total4 = Bv * H4;                 // 442368
    if (tid >= total4) return;

    const int b  = tid / H4;
    const int v4 = tid - b * H4;                // float4 index within plane

    const float4* q4  = (const float4*)q_in  + b * 4 * H4 + v4;
    const float4* qr4 = (const float4*)q_ref + b * 4 * H4 + v4;
    const float4* r4  = (const float4*)r_in  + b * Kv * H4 + v4;
    const float4* rr4 = (const float4*)r_ref + b * Kv * H4 + v4;

    float4 qa[4], qq[4], rv[3], rr[3];
#pragma unroll
    for (int c = 0; c < 4; c++) {
        qa[c] = __ldcs(q4  + c * H4);
        qq[c] = __ldcs(qr4 + c * H4);
    }
#pragma unroll
    for (int k = 0; k < Kv; k++) {
        rv[k] = __ldcs(r4  + k * H4);
        rr[k] = __ldcs(rr4 + k * H4);
    }

    const float w0 = __ldg(gate_w + 0);
    const float w1 = __ldg(gate_w + 1);
    const float w2 = __ldg(gate_w + 2);
    const float w3b = __ldg(gate_w + 3) + __ldg(gate_b);

    // ---- 4 lanes ----
    float Rn0[9], Rn1[9], Rn2[9], Rn3[9];
    float qo0[4], qo1[4], qo2[4], qo3[4];
    float om0, om1, om2, om3;

    voxel_math(qa[0].x, qa[1].x, qa[2].x, qa[3].x,
               qq[0].x, qq[1].x, qq[2].x, qq[3].x,
               rv[0].x, rv[1].x, rv[2].x,
               rr[0].x, rr[1].x, rr[2].x,
               w0, w1, w2, w3b, Rn0, qo0, om0);
    voxel_math(qa[0].y, qa[1].y, qa[2].y, qa[3].y,
               qq[0].y, qq[1].y, qq[2].y, qq[3].y,
               rv[0].y, rv[1].y, rv[2].y,
               rr[0].y, rr[1].y, rr[2].y,
               w0, w1, w2, w3b, Rn1, qo1, om1);
    voxel_math(qa[0].z, qa[1].z, qa[2].z, qa[3].z,
               qq[0].z, qq[1].z, qq[2].z, qq[3].z,
               rv[0].z, rv[1].z, rv[2].z,
               rr[0].z, rr[1].z, rr[2].z,
               w0, w1, w2, w3b, Rn2, qo2, om2);
    voxel_math(qa[0].w, qa[1].w, qa[2].w, qa[3].w,
               qq[0].w, qq[1].w, qq[2].w, qq[3].w,
               rv[0].w, rv[1].w, rv[2].w,
               rr[0].w, rr[1].w, rr[2].w,
               w0, w1, w2, w3b, Rn3, qo3, om3);

    // ---- streaming stores (evict-first; zero reuse) ----
    const int OFF_R = Bv * 9 * H4;              // float4 units
    const int OFF_Q = OFF_R + Bv * Kv * H4;

    float4* ub = (float4*)out + b * 9 * H4 + v4;
#pragma unroll
    for (int m = 0; m < 9; m++) {
        __stcs(ub + m * H4, make_float4(Rn0[m], Rn1[m], Rn2[m], Rn3[m]));
    }

    float4* rb = (float4*)out + OFF_R + b * Kv * H4 + v4;
#pragma unroll
    for (int k = 0; k < Kv; k++) {
        float4 o;
        o.x = om0 * rv[k].x + (1.0f - om0) * rr[k].x;
        o.y = om1 * rv[k].y + (1.0f - om1) * rr[k].y;
        o.z = om2 * rv[k].z + (1.0f - om2) * rr[k].z;
        o.w = om3 * rv[k].w + (1.0f - om3) * rr[k].w;
        __stcs(rb + k * H4, o);
    }

    float4* qb = (float4*)out + OFF_Q + b * 4 * H4 + v4;
#pragma unroll
    for (int c = 0; c < 4; c++) {
        __stcs(qb + c * H4, make_float4(qo0[c], qo1[c], qo2[c], qo3[c]));
    }
}

extern "C" void kernel_launch(void* const* d_in, const int* in_sizes, int n_in,
                              void* d_out, int out_size) {
    const float* r_in   = (const float*)d_in[1];
    const float* q_in   = (const float*)d_in[2];
    const float* r_ref  = (const float*)d_in[4];
    const float* q_ref  = (const float*)d_in[5];
    const float* gate_w = (const float*)d_in[6];
    const float* gate_b = (const float*)d_in[7];
    float* out = (float*)d_out;

    const int total4 = Bv * H4;                 // 442368 threads
    const int threads = 256;
    const int blocks = (total4 + threads - 1) / threads;   // 1728
    consensus_field_kernel<<<blocks, threads>>>(r_in, q_in, r_ref, q_ref,
                                                gate_w, gate_b, out);
}